// round 6
// baseline (speedup 1.0000x reference)
#include <cuda_runtime.h>
#include <cstdint>

#define B_DIM 32
#define S_LEN 2048
#define I_DIM 256
#define H_DIM 256

// ---------------------------------------------------------------------------
// helpers
// ---------------------------------------------------------------------------
__device__ __forceinline__ unsigned long long ffma2(unsigned long long a,
                                                    unsigned long long b,
                                                    unsigned long long c) {
    unsigned long long d;
    asm("fma.rn.f32x2 %0, %1, %2, %3;" : "=l"(d) : "l"(a), "l"(b), "l"(c));
    return d;
}
__device__ __forceinline__ unsigned long long pack2(float x, float y) {
    unsigned long long d;
    asm("mov.b64 %0, {%1, %2};" : "=l"(d) : "f"(x), "f"(y));
    return d;
}
__device__ __forceinline__ float2 unpack2(unsigned long long v) {
    float2 r;
    asm("mov.b64 {%0, %1}, %2;" : "=f"(r.x), "=f"(r.y) : "l"(v));
    return r;
}
__device__ __forceinline__ uint32_t smem_u32(const void* p) {
    uint32_t a;
    asm("{ .reg .u64 t; cvta.to.shared.u64 t, %1; cvt.u32.u64 %0, t; }"
        : "=r"(a) : "l"(p));
    return a;
}
__device__ __forceinline__ uint32_t mapa_u32(uint32_t a, uint32_t rank) {
    uint32_t d;
    asm("mapa.shared::cluster.u32 %0, %1, %2;" : "=r"(d) : "r"(a), "r"(rank));
    return d;
}
__device__ __forceinline__ void mbar_init(uint32_t mbar, uint32_t count) {
    asm volatile("mbarrier.init.shared.b64 [%0], %1;" :: "r"(mbar), "r"(count) : "memory");
}
__device__ __forceinline__ void mbar_arrive(uint32_t mbar) {
    asm volatile("mbarrier.arrive.shared.b64 _, [%0];" :: "r"(mbar) : "memory");
}
__device__ __forceinline__ void mbar_expect_tx(uint32_t mbar, uint32_t bytes) {
    asm volatile("mbarrier.arrive.expect_tx.shared.b64 _, [%0], %1;"
                 :: "r"(mbar), "r"(bytes) : "memory");
}
__device__ __forceinline__ void mbar_wait(uint32_t mbar, uint32_t parity) {
    asm volatile(
        "{\n\t.reg .pred P;\n\t"
        "WL%=:\n\t"
        "mbarrier.try_wait.parity.acquire.cta.shared::cta.b64 P, [%0], %1, 0x989680;\n\t"
        "@!P bra WL%=;\n\t}"
        :: "r"(mbar), "r"(parity) : "memory");
}
__device__ __forceinline__ void st_async_f32(uint32_t raddr, float v, uint32_t rmbar) {
    asm volatile(
        "st.async.shared::cluster.mbarrier::complete_tx::bytes.f32 [%0], %1, [%2];"
        :: "r"(raddr), "f"(v), "r"(rmbar) : "memory");
}
__device__ __forceinline__ float tanh_fast(float x) {
    float r;
    asm("tanh.approx.f32 %0, %1;" : "=f"(r) : "f"(x));
    return r;
}

// ---------------------------------------------------------------------------
// Kernel 1: xw[b,s,h] = x[b,s,:] . Wx_w[h,:] + Wx_b[h]  (into outputs region)
// ---------------------------------------------------------------------------
__global__ __launch_bounds__(256, 2)
void xw_gemm_kernel(const float* __restrict__ A, const float* __restrict__ W,
                    const float* __restrict__ bias, float* __restrict__ C) {
    __shared__ __align__(16) float As[16][128];
    __shared__ __align__(16) float Bs[16][128];

    const int tid = threadIdx.x;
    const int tx = tid & 15;
    const int ty = tid >> 4;
    const long bm = (long)blockIdx.x * 128;
    const long bn = (long)blockIdx.y * 128;

    const float* Ab = A + bm * I_DIM;
    const float* Wb = W + bn * I_DIM;

    unsigned long long acc[8][4];
#pragma unroll
    for (int i = 0; i < 8; i++)
#pragma unroll
        for (int j = 0; j < 4; j++) acc[i][j] = 0ull;

    for (int k0 = 0; k0 < I_DIM; k0 += 16) {
#pragma unroll
        for (int f = tid; f < 512; f += 256) {
            int row = f >> 2, kq = f & 3;
            float4 va = *(const float4*)(Ab + (long)row * I_DIM + k0 + kq * 4);
            As[kq * 4 + 0][row] = va.x; As[kq * 4 + 1][row] = va.y;
            As[kq * 4 + 2][row] = va.z; As[kq * 4 + 3][row] = va.w;
            float4 vw = *(const float4*)(Wb + (long)row * I_DIM + k0 + kq * 4);
            Bs[kq * 4 + 0][row] = vw.x; Bs[kq * 4 + 1][row] = vw.y;
            Bs[kq * 4 + 2][row] = vw.z; Bs[kq * 4 + 3][row] = vw.w;
        }
        __syncthreads();
#pragma unroll
        for (int k = 0; k < 16; k++) {
            const float4* As4 = (const float4*)&As[k][0];
            const ulonglong2* Bs2 = (const ulonglong2*)&Bs[k][0];
            float4 a0 = As4[ty * 2], a1 = As4[ty * 2 + 1];
            ulonglong2 bA = Bs2[tx * 2], bB = Bs2[tx * 2 + 1];
            unsigned long long bp[4] = {bA.x, bA.y, bB.x, bB.y};
            float av[8] = {a0.x, a0.y, a0.z, a0.w, a1.x, a1.y, a1.z, a1.w};
#pragma unroll
            for (int i = 0; i < 8; i++) {
                unsigned long long ap = pack2(av[i], av[i]);
#pragma unroll
                for (int j = 0; j < 4; j++) acc[i][j] = ffma2(ap, bp[j], acc[i][j]);
            }
        }
        __syncthreads();
    }

    float bv[8];
#pragma unroll
    for (int j = 0; j < 8; j++) bv[j] = bias[bn + tx * 8 + j];
#pragma unroll
    for (int i = 0; i < 8; i++) {
        long m = bm + ty * 8 + i;
        float* Crow = C + m * (long)H_DIM + bn + tx * 8;
        float2 c0 = unpack2(acc[i][0]), c1 = unpack2(acc[i][1]);
        float2 c2 = unpack2(acc[i][2]), c3 = unpack2(acc[i][3]);
        *(float4*)(Crow)     = make_float4(c0.x + bv[0], c0.y + bv[1], c1.x + bv[2], c1.y + bv[3]);
        *(float4*)(Crow + 4) = make_float4(c2.x + bv[4], c2.y + bv[5], c3.x + bv[6], c3.y + bv[7]);
    }
}

// ---------------------------------------------------------------------------
// Kernel 2: recurrence, BARRIER-FREE inner loop.
// 2-CTA cluster per batch row, 256 threads. Thread (jl 0..127, kc 0..1) owns
// output jg = rank*128+jl with k split: 64 k from self half + 64 k from peer
// half (128 weights in regs). ALL h traffic is st.async messages:
//   kc0 lane -> own  hS[b][jl] (tx on own  mbS[b])
//   kc1 lane -> peer hP[b][jl] (tx on peer mbP[b])
// Every thread sends exactly one counted message per step => the mbar pair is
// a full cluster rendezvous => max warp skew 1 step => 2 buffers suffice and
// NO __syncthreads is needed in the loop. Self-wait is fast-path; self-half
// FMAs overlap the peer transit.
// ---------------------------------------------------------------------------
__global__ __launch_bounds__(256, 1) __cluster_dims__(2, 1, 1)
void srnn_recur_kernel(const float* __restrict__ Wh, float* __restrict__ out) {
    __shared__ __align__(16) float hS[2][128];   // self-half h (st.async from own kc0)
    __shared__ __align__(16) float hP[2][128];   // peer-half h (st.async from peer kc1)
    __shared__ __align__(8) unsigned long long mbS[2];
    __shared__ __align__(8) unsigned long long mbP[2];

    const int rank = blockIdx.x;
    const int row  = blockIdx.y;
    const int t    = threadIdx.x;
    const int jl   = t >> 1;          // 0..127 output index
    const int kc   = t & 1;           // k sub-chunk within each half
    const int jg   = rank * 128 + jl;

    // --- preload 128 weights: 64 from self half, 64 from peer half ---
    unsigned long long wSA[16], wSB[16], wPA[16], wPB[16];
    {
        const float* wS = Wh + (long)jg * H_DIM + (rank * 128 + kc * 64);
        const float* wP = Wh + (long)jg * H_DIM + ((rank ^ 1) * 128 + kc * 64);
#pragma unroll
        for (int u = 0; u < 16; u++) {
            ulonglong2 a = *(const ulonglong2*)(wS + u * 4);
            wSA[u] = a.x; wSB[u] = a.y;
            ulonglong2 b = *(const ulonglong2*)(wP + u * 4);
            wPA[u] = b.x; wPB[u] = b.y;
        }
    }

    const uint32_t mS0 = smem_u32(&mbS[0]), mS1 = smem_u32(&mbS[1]);
    const uint32_t mP0 = smem_u32(&mbP[0]), mP1 = smem_u32(&mbP[1]);

    if (t == 0) {
        mbar_init(mS0, 1); mbar_init(mS1, 1);
        mbar_init(mP0, 1); mbar_init(mP1, 1);
        mbar_arrive(mS0);            // phase 0 of buffer 0: h0 known, complete
        mbar_arrive(mP0);
        mbar_expect_tx(mS1, 512);    // armed for step-0 sends (-> buffer 1)
        mbar_expect_tx(mP1, 512);
    }
    if (t < 128) { hS[0][t] = 0.0f; hP[0][t] = 0.0f; }
    __syncthreads();
    asm volatile("barrier.cluster.arrive.aligned;" ::: "memory");
    asm volatile("barrier.cluster.wait.aligned;" ::: "memory");

    // destinations: kc0 -> own hS slot; kc1 -> peer hP slot (same jl)
    const uint32_t dst0 = mapa_u32(smem_u32(kc ? (void*)&hP[0][jl] : (void*)&hS[0][jl]),
                                   kc ? (rank ^ 1) : rank);
    const uint32_t dst1 = mapa_u32(smem_u32(kc ? (void*)&hP[1][jl] : (void*)&hS[1][jl]),
                                   kc ? (rank ^ 1) : rank);
    const uint32_t dmb0 = mapa_u32(kc ? mP0 : mS0, kc ? (rank ^ 1) : rank);
    const uint32_t dmb1 = mapa_u32(kc ? mP1 : mS1, kc ? (rank ^ 1) : rank);

    float* xwp = out + (long)row * S_LEN * H_DIM + jg;
    float xw_next = xwp[0];

    for (int step = 0; step < S_LEN; step++) {
        const int b = step & 1;
        const uint32_t par = (step >> 1) & 1;
        float xw_cur = xw_next;
        if (step + 1 < S_LEN)
            xw_next = xwp[(long)(step + 1) * H_DIM];

        unsigned long long a0 = 0ull, a1 = 0ull, a2 = 0ull, a3 = 0ull;

        // ---- wait self half (fast path: own CTA's sends, short latency)
        mbar_wait(b ? mS1 : mS0, par);
        if (t == 0) mbar_expect_tx(b ? mS1 : mS0, 512);  // re-arm for step+2

        {
            const ulonglong2* h2 = (const ulonglong2*)&hS[b][kc * 64];
#pragma unroll
            for (int u = 0; u < 16; u += 2) {
                ulonglong2 h0 = h2[u], h1 = h2[u + 1];
                a0 = ffma2(h0.x, wSA[u], a0);
                a1 = ffma2(h0.y, wSB[u], a1);
                a2 = ffma2(h1.x, wSA[u + 1], a2);
                a3 = ffma2(h1.y, wSB[u + 1], a3);
            }
        }

        // ---- wait peer half (transit hidden behind self-half FMAs)
        mbar_wait(b ? mP1 : mP0, par);
        if (t == 0) mbar_expect_tx(b ? mP1 : mP0, 512);

        {
            const ulonglong2* h2 = (const ulonglong2*)&hP[b][kc * 64];
#pragma unroll
            for (int u = 0; u < 16; u += 2) {
                ulonglong2 h0 = h2[u], h1 = h2[u + 1];
                a0 = ffma2(h0.x, wPA[u], a0);
                a1 = ffma2(h0.y, wPB[u], a1);
                a2 = ffma2(h1.x, wPA[u + 1], a2);
                a3 = ffma2(h1.y, wPB[u + 1], a3);
            }
        }

        float2 f0 = unpack2(a0), f1 = unpack2(a1);
        float2 f2 = unpack2(a2), f3 = unpack2(a3);
        float s = ((f0.x + f0.y) + (f1.x + f1.y)) +
                  ((f2.x + f2.y) + (f3.x + f3.y));
        s += __shfl_xor_sync(0xffffffffu, s, 1);   // both kc lanes: full sum

        float v = tanh_fast(s + xw_cur);

        // every thread sends exactly one counted message -> rendezvous
        st_async_f32(b ? dst0 : dst1, v, b ? dmb0 : dmb1);

        if (kc == 1) {
            xwp[(long)step * H_DIM] = v;          // in-place output
        } else if (step == S_LEN - 1) {
            out[(long)B_DIM * S_LEN * H_DIM + (long)row * H_DIM + jg] = v;
        }
    }

    // keep smem alive until peer's in-flight st.asyncs land
    asm volatile("barrier.cluster.arrive.aligned;" ::: "memory");
    asm volatile("barrier.cluster.wait.aligned;" ::: "memory");
}

// ---------------------------------------------------------------------------
// Launch
// ---------------------------------------------------------------------------
extern "C" void kernel_launch(void* const* d_in, const int* in_sizes, int n_in,
                              void* d_out, int out_size) {
    const float* x    = (const float*)d_in[0];  // [B,S,I]
    const float* Wx_w = (const float*)d_in[1];  // [H,I]
    const float* Wx_b = (const float*)d_in[2];  // [H]
    const float* Wh_w = (const float*)d_in[3];  // [H,H]
    float* out = (float*)d_out;                 // [B,S,H] ++ [B,H]

    dim3 g1((B_DIM * S_LEN) / 128, H_DIM / 128);
    xw_gemm_kernel<<<g1, 256>>>(x, Wx_w, Wx_b, out);

    dim3 g2(2, B_DIM);
    srnn_recur_kernel<<<g2, 256>>>(Wh_w, out);
}